// round 13
// baseline (speedup 1.0000x reference)
#include <cuda_runtime.h>
#include <cstdint>
#include <math.h>

typedef unsigned long long ull;

// Problem dims (fixed by the reference)
#define BB 2048
#define SS 50
#define EE 256
#define HH 512
#define G4 (4*HH)       // 2048
#define WW 256
#define LL 50
#define GCAT (G4 + WW)  // 2304 : [interleaved dec gates | blend2]

#define PARTITIONABLE 1

// ---------------- scratch (static device globals; no allocation) ----------------
__device__ __align__(16) float g_X[SS*BB*EE];        // gathered embeddings, [s][b][e]
__device__ __align__(16) float g_gates[SS*BB*G4];    // encoder input gate pre-acts (interleaved)
__device__ __align__(16) float g_enc[BB*SS*HH];      // encoder hidden states [b][s][h]
__device__ __align__(16) float g_blend1[BB*SS*WW];   // W1 @ enc_states, [b][s][w]
__device__ __align__(16) float g_blend2[BB*WW];
__device__ __align__(16) float g_h0[BB*HH];
__device__ __align__(16) float g_h1[BB*HH];
__device__ __align__(16) float g_c[BB*HH];
__device__ __align__(16) float g_bias_encI[G4];      // interleaved enc bias
__device__ __align__(16) float g_bias_catI[GCAT];    // [interleaved dec bias | 0]
__device__ __align__(16) float g_WihP[G4*EE];        // interleaved-row enc_Wih
__device__ __align__(16) float g_WhhP[G4*HH];        // interleaved-row enc_Whh
__device__ __align__(16) float g_WcatP[GCAT*HH];     // [interleaved dec_Whh ; W2]
__device__ unsigned char g_mask[BB*SS];

// ---------------- Threefry-2x32-20 (exact JAX algorithm) ----------------
__device__ __forceinline__ uint32_t rotl32(uint32_t v, int r) {
    return (v << r) | (v >> (32 - r));
}

__device__ __forceinline__ void tf2x32(uint32_t k0, uint32_t k1,
                                       uint32_t& x0, uint32_t& x1) {
    const uint32_t ks2 = k0 ^ k1 ^ 0x1BD11BDAu;
    x0 += k0; x1 += k1;
    x0 += x1; x1 = rotl32(x1, 13); x1 ^= x0;
    x0 += x1; x1 = rotl32(x1, 15); x1 ^= x0;
    x0 += x1; x1 = rotl32(x1, 26); x1 ^= x0;
    x0 += x1; x1 = rotl32(x1,  6); x1 ^= x0;
    x0 += k1; x1 += ks2 + 1u;
    x0 += x1; x1 = rotl32(x1, 17); x1 ^= x0;
    x0 += x1; x1 = rotl32(x1, 29); x1 ^= x0;
    x0 += x1; x1 = rotl32(x1, 16); x1 ^= x0;
    x0 += x1; x1 = rotl32(x1, 24); x1 ^= x0;
    x0 += ks2; x1 += k0 + 2u;
    x0 += x1; x1 = rotl32(x1, 13); x1 ^= x0;
    x0 += x1; x1 = rotl32(x1, 15); x1 ^= x0;
    x0 += x1; x1 = rotl32(x1, 26); x1 ^= x0;
    x0 += x1; x1 = rotl32(x1,  6); x1 ^= x0;
    x0 += k0; x1 += k1 + 3u;
    x0 += x1; x1 = rotl32(x1, 17); x1 ^= x0;
    x0 += x1; x1 = rotl32(x1, 29); x1 ^= x0;
    x0 += x1; x1 = rotl32(x1, 16); x1 ^= x0;
    x0 += x1; x1 = rotl32(x1, 24); x1 ^= x0;
    x0 += k1; x1 += ks2 + 4u;
    x0 += x1; x1 = rotl32(x1, 13); x1 ^= x0;
    x0 += x1; x1 = rotl32(x1, 15); x1 ^= x0;
    x0 += x1; x1 = rotl32(x1, 26); x1 ^= x0;
    x0 += x1; x1 = rotl32(x1,  6); x1 ^= x0;
    x0 += ks2; x1 += k0 + 5u;
}

__device__ __forceinline__ void derive_key(int step, uint32_t& K0, uint32_t& K1) {
#if PARTITIONABLE
    uint32_t a = 0u, b = (uint32_t)step;
    tf2x32(0u, 42u, a, b);
    K0 = a; K1 = b;
#else
    const int la = (step < 25) ? 2*step : 2*step - 50;
    uint32_t a0 = (uint32_t)la,     a1 = (uint32_t)(la + 50);
    uint32_t b0 = (uint32_t)(la+1), b1 = (uint32_t)(la + 51);
    tf2x32(0u, 42u, a0, a1);
    tf2x32(0u, 42u, b0, b1);
    if (step < 25) { K0 = a0; K1 = b0; } else { K0 = a1; K1 = b1; }
#endif
}

__device__ __forceinline__ uint32_t rand_bits(uint32_t K0, uint32_t K1, uint32_t i) {
#if PARTITIONABLE
    uint32_t x0 = 0u, x1 = i;
    tf2x32(K0, K1, x0, x1);
    return x0 ^ x1;
#else
    const uint32_t half = (BB*SS) / 2;
    if (i < half) { uint32_t x0 = i, x1 = i + half; tf2x32(K0, K1, x0, x1); return x0; }
    else          { uint32_t x0 = i - half, x1 = i; tf2x32(K0, K1, x0, x1); return x1; }
#endif
}

__device__ __forceinline__ float sigm(float x) { return 1.f / (1.f + expf(-x)); }

// ---------------- fused GEMM (+ optional LSTM-cell epilogue) ----------------
// C-logical[M,N] = A[M,K] @ Bw[N,K]^T. Tile 128x256, Kc=16, 256 threads,
// 8x16 micro-tile via packed fma.rn.f32x2, double-buffered smem.
// Columns < cellCols (multiple of 256) are interleaved LSTM gates (col=4j+gate):
//   gatequad += (D ? D[row] : bias); cell update -> write c, hOut, (encOut[sIdx]).
// Columns >= cellCols: plain write to C[row*cstride + col - coloff] (+bias[col]).
__global__ __launch_bounds__(256) void gemm_fused(
    const float* __restrict__ A, const float* __restrict__ Bw,
    float* C, int cstride, int coloff,
    const float* __restrict__ D, const float* __restrict__ bias,
    float* cSt, float* hOut, float* encOut, int sIdx,
    int cellCols, int K)
{
    __shared__ float As[2][16][128];
    __shared__ float Bs[2][16][256];
    const int tid = threadIdx.x;
    const int bm = blockIdx.y << 7;
    const int bn = blockIdx.x << 8;

    const int r0 = tid >> 2;            // 0..63
    const int kq = (tid & 3) << 2;      // 0,4,8,12

    const float* Ap0 = A  + (size_t)(bm + r0) * K + kq;
    const float* Ap1 = Ap0 + (size_t)64 * K;
    const float* Bp0 = Bw + (size_t)(bn + r0) * K + kq;
    const float* Bp1 = Bp0 + (size_t)64  * K;
    const float* Bp2 = Bp0 + (size_t)128 * K;
    const float* Bp3 = Bp0 + (size_t)192 * K;

    const int tm = (tid >> 4) << 3;     // 0..120
    const int tn = (tid & 15) << 4;     // 0..240

    ull acc2[8][8];
#pragma unroll
    for (int i = 0; i < 8; ++i)
#pragma unroll
        for (int j = 0; j < 8; ++j) acc2[i][j] = 0ull;

    const int nk = K >> 4;

    // prime buffer 0
    {
        float4 a0 = *(const float4*)Ap0;
        float4 a1 = *(const float4*)Ap1;
        float4 b0 = *(const float4*)Bp0;
        float4 b1 = *(const float4*)Bp1;
        float4 b2 = *(const float4*)Bp2;
        float4 b3 = *(const float4*)Bp3;
        As[0][kq+0][r0]     = a0.x; As[0][kq+1][r0]     = a0.y; As[0][kq+2][r0]     = a0.z; As[0][kq+3][r0]     = a0.w;
        As[0][kq+0][r0+64]  = a1.x; As[0][kq+1][r0+64]  = a1.y; As[0][kq+2][r0+64]  = a1.z; As[0][kq+3][r0+64]  = a1.w;
        Bs[0][kq+0][r0]     = b0.x; Bs[0][kq+1][r0]     = b0.y; Bs[0][kq+2][r0]     = b0.z; Bs[0][kq+3][r0]     = b0.w;
        Bs[0][kq+0][r0+64]  = b1.x; Bs[0][kq+1][r0+64]  = b1.y; Bs[0][kq+2][r0+64]  = b1.z; Bs[0][kq+3][r0+64]  = b1.w;
        Bs[0][kq+0][r0+128] = b2.x; Bs[0][kq+1][r0+128] = b2.y; Bs[0][kq+2][r0+128] = b2.z; Bs[0][kq+3][r0+128] = b2.w;
        Bs[0][kq+0][r0+192] = b3.x; Bs[0][kq+1][r0+192] = b3.y; Bs[0][kq+2][r0+192] = b3.z; Bs[0][kq+3][r0+192] = b3.w;
    }
    __syncthreads();

    int cur = 0;
    for (int kt = 0; kt < nk; ++kt) {
        const bool hasNext = (kt + 1 < nk);
        float4 a0, a1, b0, b1, b2, b3;
        if (hasNext) {
            const int off = (kt + 1) << 4;
            a0 = *(const float4*)(Ap0 + off);
            a1 = *(const float4*)(Ap1 + off);
            b0 = *(const float4*)(Bp0 + off);
            b1 = *(const float4*)(Bp1 + off);
            b2 = *(const float4*)(Bp2 + off);
            b3 = *(const float4*)(Bp3 + off);
        }
#pragma unroll
        for (int kk = 0; kk < 16; ++kk) {
            const float4 x0 = *(const float4*)&As[cur][kk][tm];
            const float4 x1 = *(const float4*)&As[cur][kk][tm + 4];
            const ull* bp = (const ull*)&Bs[cur][kk][tn];
            ull bk[8];
#pragma unroll
            for (int j = 0; j < 8; ++j) bk[j] = bp[j];
            const float av[8] = {x0.x,x0.y,x0.z,x0.w,x1.x,x1.y,x1.z,x1.w};
#pragma unroll
            for (int i = 0; i < 8; ++i) {
                ull a2;
                const unsigned int ai = __float_as_uint(av[i]);
                asm("mov.b64 %0, {%1, %2};" : "=l"(a2) : "r"(ai), "r"(ai));
#pragma unroll
                for (int j = 0; j < 8; ++j)
                    asm("fma.rn.f32x2 %0, %1, %2, %0;"
                        : "+l"(acc2[i][j]) : "l"(a2), "l"(bk[j]));
            }
        }
        if (hasNext) {
            const int nxt = cur ^ 1;
            As[nxt][kq+0][r0]     = a0.x; As[nxt][kq+1][r0]     = a0.y; As[nxt][kq+2][r0]     = a0.z; As[nxt][kq+3][r0]     = a0.w;
            As[nxt][kq+0][r0+64]  = a1.x; As[nxt][kq+1][r0+64]  = a1.y; As[nxt][kq+2][r0+64]  = a1.z; As[nxt][kq+3][r0+64]  = a1.w;
            Bs[nxt][kq+0][r0]     = b0.x; Bs[nxt][kq+1][r0]     = b0.y; Bs[nxt][kq+2][r0]     = b0.z; Bs[nxt][kq+3][r0]     = b0.w;
            Bs[nxt][kq+0][r0+64]  = b1.x; Bs[nxt][kq+1][r0+64]  = b1.y; Bs[nxt][kq+2][r0+64]  = b1.z; Bs[nxt][kq+3][r0+64]  = b1.w;
            Bs[nxt][kq+0][r0+128] = b2.x; Bs[nxt][kq+1][r0+128] = b2.y; Bs[nxt][kq+2][r0+128] = b2.z; Bs[nxt][kq+3][r0+128] = b2.w;
            Bs[nxt][kq+0][r0+192] = b3.x; Bs[nxt][kq+1][r0+192] = b3.y; Bs[nxt][kq+2][r0+192] = b3.z; Bs[nxt][kq+3][r0+192] = b3.w;
            __syncthreads();
            cur = nxt;
        }
    }

    const int ac0 = bn + tn;
#pragma unroll
    for (int i = 0; i < 8; ++i) {
        float accf[16];
#pragma unroll
        for (int j = 0; j < 8; ++j) {
            unsigned int lo, hi;
            asm("mov.b64 {%0, %1}, %2;" : "=r"(lo), "=r"(hi) : "l"(acc2[i][j]));
            accf[2*j]   = __uint_as_float(lo);
            accf[2*j+1] = __uint_as_float(hi);
        }
        const int row = bm + tm + i;
        if (ac0 < cellCols) {
            // interleaved LSTM-cell epilogue: 4 gate-quads -> 4 consecutive j
            const float* addp = D ? (D + (size_t)row * (size_t)G4 + ac0)
                                  : (bias + ac0);
            const int jb = ac0 >> 2;
            float4 cv = *(const float4*)(cSt + (size_t)row * HH + jb);
            float* cvp = &cv.x;
            float hv[4];
#pragma unroll
            for (int q = 0; q < 4; ++q) {
                const float4 ad = *(const float4*)(addp + 4*q);
                const float xi = accf[4*q+0] + ad.x;
                const float xf = accf[4*q+1] + ad.y;
                const float xg = accf[4*q+2] + ad.z;
                const float xo = accf[4*q+3] + ad.w;
                const float cc = sigm(xf) * cvp[q] + sigm(xi) * tanhf(xg);
                cvp[q] = cc;
                hv[q] = sigm(xo) * tanhf(cc);
            }
            *(float4*)(cSt + (size_t)row * HH + jb) = cv;
            const float4 hvv = make_float4(hv[0], hv[1], hv[2], hv[3]);
            *(float4*)(hOut + (size_t)row * HH + jb) = hvv;
            if (encOut)
                *(float4*)(encOut + ((size_t)row * SS + sIdx) * HH + jb) = hvv;
        } else {
            float* Cp = C + (size_t)row * cstride + (ac0 - coloff);
#pragma unroll
            for (int q = 0; q < 4; ++q) {
                float4 v = make_float4(accf[4*q], accf[4*q+1],
                                       accf[4*q+2], accf[4*q+3]);
                if (bias) {
                    const float4 bb = *(const float4*)(bias + ac0 + 4*q);
                    v.x += bb.x; v.y += bb.y; v.z += bb.z; v.w += bb.w;
                }
                *(float4*)(Cp + 4*q) = v;
            }
        }
    }
}

// ---------------- prep kernels ----------------
// interleave permutation: new row r <- old row (r&3)*H + (r>>2)
__global__ void prep_misc(const float* __restrict__ ebih, const float* __restrict__ ebhh,
                          const float* __restrict__ dbih, const float* __restrict__ dbhh)
{
    const int t = blockIdx.x * blockDim.x + threadIdx.x;
    if (t < G4) {
        const int p = (t & 3) * HH + (t >> 2);
        g_bias_encI[t] = ebih[p] + ebhh[p];
        g_bias_catI[t] = dbih[p] + dbhh[p];
    } else if (t < GCAT) {
        g_bias_catI[t] = 0.f;
    }
    if (t < BB*SS) g_mask[t] = 0;
    if (t < BB*HH) g_c[t] = 0.f;
}

__global__ void prep_w(const float* __restrict__ eWih, const float* __restrict__ eWhh,
                       const float* __restrict__ dWhh, const float* __restrict__ W2)
{
    const int E4 = EE/4, H4 = HH/4;
    const int n1 = G4*E4, n2 = G4*H4, n3 = GCAT*H4;
    int t = blockIdx.x * blockDim.x + threadIdx.x;
    if (t < n1) {
        const int row = t / E4, c4 = t % E4;
        const int p = (row & 3) * HH + (row >> 2);
        ((float4*)g_WihP)[t] = ((const float4*)eWih)[(size_t)p * E4 + c4];
        return;
    }
    t -= n1;
    if (t < n2) {
        const int row = t / H4, c4 = t % H4;
        const int p = (row & 3) * HH + (row >> 2);
        ((float4*)g_WhhP)[t] = ((const float4*)eWhh)[(size_t)p * H4 + c4];
        return;
    }
    t -= n2;
    if (t < n3) {
        const int row = t / H4, c4 = t % H4;
        float4 v;
        if (row < G4) {
            const int p = (row & 3) * HH + (row >> 2);
            v = ((const float4*)dWhh)[(size_t)p * H4 + c4];
        } else {
            v = ((const float4*)W2)[(size_t)(row - G4) * H4 + c4];
        }
        ((float4*)g_WcatP)[t] = v;
    }
}

__global__ void gather_x(const int* __restrict__ input, const float* __restrict__ emb)
{
    const int E4 = EE / 4;
    const int t = blockIdx.x * blockDim.x + threadIdx.x;
    if (t >= SS * BB * E4) return;
    const int e4 = t % E4;
    const int r  = t / E4;      // r = s*BB + b
    const int b  = r % BB;
    const int s  = r / BB;
    const int tok = input[b * SS + s];
    ((float4*)g_X)[(size_t)r * E4 + e4] = ((const float4*)emb)[(size_t)tok * E4 + e4];
}

// standalone interleaved cell (for encoder step 0 and decoder step 0)
__global__ __launch_bounds__(256) void cell_i(const float* __restrict__ gates,
                                              int rowStride, float* hOut,
                                              float* encOut, int sIdx)
{
    const int t = blockIdx.x * blockDim.x + threadIdx.x;  // over B*H
    const int b = t >> 9;
    const int j = t & (HH - 1);
    const float4 gq = *(const float4*)(gates + (size_t)b * rowStride + 4*j);
    const float cn = sigm(gq.y) * g_c[t] + sigm(gq.x) * tanhf(gq.z);
    const float hn = sigm(gq.w) * tanhf(cn);
    g_c[t] = cn;
    hOut[t] = hn;
    if (encOut) encOut[((size_t)b * SS + sIdx) * HH + j] = hn;
}

// decoder init: c0 = final encoder h
__global__ void dec_init(const float* __restrict__ hSrc)
{
    const int t = blockIdx.x * blockDim.x + threadIdx.x;
    if (t < BB*HH) g_c[t] = hSrc[t];
}

// ---------------- fused scores + log_softmax + categorical + mask ----------------
__global__ __launch_bounds__(256) void score_sample(
    const float* __restrict__ blend2, int b2stride,
    const float* __restrict__ vt, float* probs, float* tour, int step)
{
    const int b = blockIdx.x;
    const int tid = threadIdx.x;
    const int wid = tid >> 5, lane = tid & 31;
    __shared__ float b2s[WW];
    __shared__ float vts[WW];
    __shared__ float sc[SS];
    __shared__ float smm[SS];
    __shared__ float smv[SS];
    __shared__ float red[2];

    b2s[tid] = blend2[(size_t)b * b2stride + tid];
    vts[tid] = vt[tid];
    __syncthreads();

    for (int s = wid; s < SS; s += 8) {
        const float* row = g_blend1 + ((size_t)b * SS + s) * WW;
        float a = 0.f;
#pragma unroll
        for (int w = lane; w < WW; w += 32)
            a += vts[w] * tanhf(row[w] + b2s[w]);
        a += __shfl_down_sync(0xffffffffu, a, 16);
        a += __shfl_down_sync(0xffffffffu, a,  8);
        a += __shfl_down_sync(0xffffffffu, a,  4);
        a += __shfl_down_sync(0xffffffffu, a,  2);
        a += __shfl_down_sync(0xffffffffu, a,  1);
        if (lane == 0) sc[s] = a;
    }
    __syncthreads();

    if (tid < SS) {
        const float sm_ = g_mask[b * SS + tid] ? -100000.0f : sc[tid];
        uint32_t K0, K1;
        derive_key(step, K0, K1);
        const uint32_t bits = rand_bits(K0, K1, (uint32_t)(b * SS + tid));
        float u = __uint_as_float((bits >> 9) | 0x3f800000u) - 1.0f;
        u = u + 1.17549435e-38f;
        if (u < 1.17549435e-38f) u = 1.17549435e-38f;
        const float g = -logf(-logf(u));
        smm[tid] = sm_;
        smv[tid] = sm_ + g;
    }
    __syncthreads();

    if (tid == 0) {
        float best = smv[0]; int bi = 0; float mx = smm[0];
        for (int s = 1; s < SS; ++s) {
            if (smv[s] > best) { best = smv[s]; bi = s; }
            if (smm[s] > mx) mx = smm[s];
        }
        float sum = 0.f;
        for (int s = 0; s < SS; ++s) sum += expf(smm[s] - mx);
        red[0] = mx; red[1] = logf(sum);
        g_mask[b * SS + bi] = 1;
        if (tour) tour[(size_t)b * LL + step] = (float)bi;
    }
    __syncthreads();

    if (tid < SS && probs) {
        probs[((size_t)b * LL + step) * SS + tid] = (smm[tid] - red[0]) - red[1];
    }
}

// ---------------- launch ----------------
extern "C" void kernel_launch(void* const* d_in, const int* in_sizes, int n_in,
                              void* d_out, int out_size)
{
    if (n_in < 13) return;
    const int*   input = (const int*)  d_in[0];
    const float* emb   = (const float*)d_in[1];
    const float* eWih  = (const float*)d_in[2];
    const float* eWhh  = (const float*)d_in[3];
    const float* ebih  = (const float*)d_in[4];
    const float* ebhh  = (const float*)d_in[5];
    /* d_in[6] = dec_Wih : unused (decoder input is all zeros) */
    const float* dWhh  = (const float*)d_in[7];
    const float* dbih  = (const float*)d_in[8];
    const float* dbhh  = (const float*)d_in[9];
    const float* W1    = (const float*)d_in[10];
    const float* W2    = (const float*)d_in[11];
    const float* vt    = (const float*)d_in[12];

    float *pX, *pGates, *pEnc, *pB1, *pB2, *pH0, *pH1, *pC,
          *pBEI, *pBCI, *pWihP, *pWhhP, *pWcatP;
    cudaGetSymbolAddress((void**)&pX,     g_X);
    cudaGetSymbolAddress((void**)&pGates, g_gates);
    cudaGetSymbolAddress((void**)&pEnc,   g_enc);
    cudaGetSymbolAddress((void**)&pB1,    g_blend1);
    cudaGetSymbolAddress((void**)&pB2,    g_blend2);
    cudaGetSymbolAddress((void**)&pH0,    g_h0);
    cudaGetSymbolAddress((void**)&pH1,    g_h1);
    cudaGetSymbolAddress((void**)&pC,     g_c);
    cudaGetSymbolAddress((void**)&pBEI,   g_bias_encI);
    cudaGetSymbolAddress((void**)&pBCI,   g_bias_catI);
    cudaGetSymbolAddress((void**)&pWihP,  g_WihP);
    cudaGetSymbolAddress((void**)&pWhhP,  g_WhhP);
    cudaGetSymbolAddress((void**)&pWcatP, g_WcatP);
    float* hb[2] = {pH0, pH1};

    const size_t np = (size_t)BB * LL * SS;
    const size_t nt = (size_t)BB * LL;
    float* probs = ((size_t)out_size >= np)      ? (float*)d_out        : nullptr;
    float* tour  = ((size_t)out_size >= np + nt) ? ((float*)d_out + np) : nullptr;

    // prep
    prep_misc<<<4096, 256>>>(ebih, ebhh, dbih, dbhh);
    prep_w<<<2688, 256>>>(eWih, eWhh, dWhh, W2);
    gather_x<<<25600, 256>>>(input, emb);

    // encoder input projections (interleaved gates + bias), all timesteps
    gemm_fused<<<dim3(8, 800), 256>>>(pX, pWihP, pGates, G4, 0,
                                      nullptr, pBEI,
                                      nullptr, nullptr, nullptr, 0,
                                      0, EE);

    // encoder step 0: gates == input projection (h=0)
    cell_i<<<4096, 256>>>(pGates, G4, hb[0], pEnc, 0);

    // encoder recurrence with fused cell epilogue (single wave: 128 CTAs)
    for (int s = 1; s < SS; ++s) {
        gemm_fused<<<dim3(8, 16), 256>>>(hb[(s-1)&1], pWhhP, nullptr, 0, 0,
                                         pGates + (size_t)s * BB * G4, nullptr,
                                         pC, hb[s&1], pEnc, s,
                                         G4, HH);
    }

    // decoder init: c0 = enc h_final (in hb[1] after s=49), h implicit 0
    dec_init<<<4096, 256>>>(hb[1]);
    cell_i<<<4096, 256>>>(pBCI, 0, hb[0], nullptr, 0);   // -> hd_1

    // blend1 = enc_states @ W1^T (loop-invariant)
    gemm_fused<<<dim3(1, 800), 256>>>(pEnc, W1, pB1, WW, 0,
                                      nullptr, nullptr,
                                      nullptr, nullptr, nullptr, 0,
                                      0, HH);

    // decoder: one wide fused GEMM per step (144 CTAs = single wave):
    //   cols [0,2048): interleaved gates -> cell -> h_{k+2}
    //   cols [2048,2304): blend2_k = h_{k+1} @ W2^T
    for (int k = 0; k < LL; ++k) {
        gemm_fused<<<dim3(9, 16), 256>>>(hb[k&1], pWcatP, pB2, WW, G4,
                                         nullptr, pBCI,
                                         pC, hb[(k+1)&1], nullptr, 0,
                                         G4, HH);
        score_sample<<<BB, 256>>>(pB2, WW, vt, probs, tour, k);
    }
}

// round 15
// speedup vs baseline: 1.5184x; 1.5184x over previous
#include <cuda_runtime.h>
#include <cstdint>
#include <math.h>

typedef unsigned long long ull;

// Problem dims (fixed by the reference)
#define BB 2048
#define SS 50
#define EE 256
#define HH 512
#define G4 (4*HH)       // 2048
#define WW 256
#define LL 50
#define GCAT (G4 + WW)  // 2304 : [interleaved dec gates | blend2]

#define PARTITIONABLE 1

// ---------------- scratch (static device globals; no allocation) ----------------
__device__ __align__(16) float g_X[SS*BB*EE];        // gathered embeddings, [s][b][e]
__device__ __align__(16) float g_gates[SS*BB*G4];    // encoder input gate pre-acts (interleaved)
__device__ __align__(16) float g_enc[BB*SS*HH];      // encoder hidden states [b][s][h]
__device__ __align__(16) float g_blend1[BB*SS*WW];   // W1 @ enc_states, [b][s][w]
__device__ __align__(16) float g_blend2[BB*WW];
__device__ __align__(16) float g_h0[BB*HH];
__device__ __align__(16) float g_h1[BB*HH];
__device__ __align__(16) float g_c[BB*HH];
__device__ __align__(16) float g_bias_encI[G4];      // interleaved enc bias
__device__ __align__(16) float g_bias_catI[GCAT];    // [interleaved dec bias | 0]
__device__ __align__(16) float g_WihP[G4*EE];        // interleaved-row enc_Wih
__device__ __align__(16) float g_WhhP[G4*HH];        // interleaved-row enc_Whh
__device__ __align__(16) float g_WcatP[GCAT*HH];     // [interleaved dec_Whh ; W2]
__device__ unsigned char g_mask[BB*SS];

// ---------------- Threefry-2x32-20 (exact JAX algorithm) ----------------
__device__ __forceinline__ uint32_t rotl32(uint32_t v, int r) {
    return (v << r) | (v >> (32 - r));
}

__device__ __forceinline__ void tf2x32(uint32_t k0, uint32_t k1,
                                       uint32_t& x0, uint32_t& x1) {
    const uint32_t ks2 = k0 ^ k1 ^ 0x1BD11BDAu;
    x0 += k0; x1 += k1;
    x0 += x1; x1 = rotl32(x1, 13); x1 ^= x0;
    x0 += x1; x1 = rotl32(x1, 15); x1 ^= x0;
    x0 += x1; x1 = rotl32(x1, 26); x1 ^= x0;
    x0 += x1; x1 = rotl32(x1,  6); x1 ^= x0;
    x0 += k1; x1 += ks2 + 1u;
    x0 += x1; x1 = rotl32(x1, 17); x1 ^= x0;
    x0 += x1; x1 = rotl32(x1, 29); x1 ^= x0;
    x0 += x1; x1 = rotl32(x1, 16); x1 ^= x0;
    x0 += x1; x1 = rotl32(x1, 24); x1 ^= x0;
    x0 += ks2; x1 += k0 + 2u;
    x0 += x1; x1 = rotl32(x1, 13); x1 ^= x0;
    x0 += x1; x1 = rotl32(x1, 15); x1 ^= x0;
    x0 += x1; x1 = rotl32(x1, 26); x1 ^= x0;
    x0 += x1; x1 = rotl32(x1,  6); x1 ^= x0;
    x0 += k0; x1 += k1 + 3u;
    x0 += x1; x1 = rotl32(x1, 17); x1 ^= x0;
    x0 += x1; x1 = rotl32(x1, 29); x1 ^= x0;
    x0 += x1; x1 = rotl32(x1, 16); x1 ^= x0;
    x0 += x1; x1 = rotl32(x1, 24); x1 ^= x0;
    x0 += k1; x1 += ks2 + 4u;
    x0 += x1; x1 = rotl32(x1, 13); x1 ^= x0;
    x0 += x1; x1 = rotl32(x1, 15); x1 ^= x0;
    x0 += x1; x1 = rotl32(x1, 26); x1 ^= x0;
    x0 += x1; x1 = rotl32(x1,  6); x1 ^= x0;
    x0 += ks2; x1 += k0 + 5u;
}

__device__ __forceinline__ void derive_key(int step, uint32_t& K0, uint32_t& K1) {
#if PARTITIONABLE
    uint32_t a = 0u, b = (uint32_t)step;
    tf2x32(0u, 42u, a, b);
    K0 = a; K1 = b;
#else
    const int la = (step < 25) ? 2*step : 2*step - 50;
    uint32_t a0 = (uint32_t)la,     a1 = (uint32_t)(la + 50);
    uint32_t b0 = (uint32_t)(la+1), b1 = (uint32_t)(la + 51);
    tf2x32(0u, 42u, a0, a1);
    tf2x32(0u, 42u, b0, b1);
    if (step < 25) { K0 = a0; K1 = b0; } else { K0 = a1; K1 = b1; }
#endif
}

__device__ __forceinline__ uint32_t rand_bits(uint32_t K0, uint32_t K1, uint32_t i) {
#if PARTITIONABLE
    uint32_t x0 = 0u, x1 = i;
    tf2x32(K0, K1, x0, x1);
    return x0 ^ x1;
#else
    const uint32_t half = (BB*SS) / 2;
    if (i < half) { uint32_t x0 = i, x1 = i + half; tf2x32(K0, K1, x0, x1); return x0; }
    else          { uint32_t x0 = i - half, x1 = i; tf2x32(K0, K1, x0, x1); return x1; }
#endif
}

__device__ __forceinline__ float sigm(float x) { return 1.f / (1.f + expf(-x)); }

// ---------------- fused GEMM (+ optional LSTM-cell epilogue) ----------------
// C-logical[M,N] = A[M,K] @ Bw[N,K]^T. Tile 128x128, Kc=16, 256 threads,
// 8x8 micro-tile with packed fma.rn.f32x2 (8x4 u64 accumulators), double
// buffered smem. __launch_bounds__(256,2) -> 2 CTAs/SM (16 warps) to hide
// LDS latency and make recurrent grids single-wave.
// Columns < cellCols (multiple of 128): interleaved LSTM gates (col=4j+gate):
//   quad += (D ? D[row*G4+col] : bias[col]); cell -> write c, hOut, encOut.
// Columns >= cellCols: plain write C[row*cstride + col - coloff] (+bias[col]).
__global__ __launch_bounds__(256, 2) void gemm_fused(
    const float* __restrict__ A, const float* __restrict__ Bw,
    float* C, int cstride, int coloff,
    const float* __restrict__ D, const float* __restrict__ bias,
    float* cSt, float* hOut, float* encOut, int sIdx,
    int cellCols, int K)
{
    __shared__ float As[2][16][128];
    __shared__ float Bs[2][16][128];
    const int tid = threadIdx.x;
    const int bm = blockIdx.y << 7;
    const int bn = blockIdx.x << 7;

    const int r0 = tid >> 2;            // 0..63
    const int kq = (tid & 3) << 2;      // 0,4,8,12

    const float* Ap0 = A  + (size_t)(bm + r0)      * K + kq;
    const float* Ap1 = A  + (size_t)(bm + r0 + 64) * K + kq;
    const float* Bp0 = Bw + (size_t)(bn + r0)      * K + kq;
    const float* Bp1 = Bw + (size_t)(bn + r0 + 64) * K + kq;

    const int tm = (tid >> 4) << 3;     // row micro-offset
    const int tn = (tid & 15) << 3;     // col micro-offset

    ull acc2[8][4];
#pragma unroll
    for (int i = 0; i < 8; ++i)
#pragma unroll
        for (int j = 0; j < 4; ++j) acc2[i][j] = 0ull;

    const int nk = K >> 4;

    float4 a0 = *(const float4*)Ap0;
    float4 a1 = *(const float4*)Ap1;
    float4 b0 = *(const float4*)Bp0;
    float4 b1 = *(const float4*)Bp1;

    int cur = 0;
    As[0][kq+0][r0]    = a0.x; As[0][kq+1][r0]    = a0.y; As[0][kq+2][r0]    = a0.z; As[0][kq+3][r0]    = a0.w;
    As[0][kq+0][r0+64] = a1.x; As[0][kq+1][r0+64] = a1.y; As[0][kq+2][r0+64] = a1.z; As[0][kq+3][r0+64] = a1.w;
    Bs[0][kq+0][r0]    = b0.x; Bs[0][kq+1][r0]    = b0.y; Bs[0][kq+2][r0]    = b0.z; Bs[0][kq+3][r0]    = b0.w;
    Bs[0][kq+0][r0+64] = b1.x; Bs[0][kq+1][r0+64] = b1.y; Bs[0][kq+2][r0+64] = b1.z; Bs[0][kq+3][r0+64] = b1.w;
    __syncthreads();

    for (int kt = 0; kt < nk; ++kt) {
        const bool hasNext = (kt + 1 < nk);
        if (hasNext) {
            const int off = (kt + 1) << 4;
            a0 = *(const float4*)(Ap0 + off);
            a1 = *(const float4*)(Ap1 + off);
            b0 = *(const float4*)(Bp0 + off);
            b1 = *(const float4*)(Bp1 + off);
        }
#pragma unroll
        for (int kk = 0; kk < 16; ++kk) {
            const float4 x0 = *(const float4*)&As[cur][kk][tm];
            const float4 x1 = *(const float4*)&As[cur][kk][tm + 4];
            const ull* bp = (const ull*)&Bs[cur][kk][tn];
            ull bpk[4];
            bpk[0] = bp[0]; bpk[1] = bp[1]; bpk[2] = bp[2]; bpk[3] = bp[3];
            const float av[8] = {x0.x,x0.y,x0.z,x0.w,x1.x,x1.y,x1.z,x1.w};
#pragma unroll
            for (int i = 0; i < 8; ++i) {
                ull a2;
                const unsigned int ai = __float_as_uint(av[i]);
                asm("mov.b64 %0, {%1, %2};" : "=l"(a2) : "r"(ai), "r"(ai));
#pragma unroll
                for (int j = 0; j < 4; ++j) {
                    asm("fma.rn.f32x2 %0, %1, %2, %0;"
                        : "+l"(acc2[i][j]) : "l"(a2), "l"(bpk[j]));
                }
            }
        }
        if (hasNext) {
            const int nxt = cur ^ 1;
            As[nxt][kq+0][r0]    = a0.x; As[nxt][kq+1][r0]    = a0.y; As[nxt][kq+2][r0]    = a0.z; As[nxt][kq+3][r0]    = a0.w;
            As[nxt][kq+0][r0+64] = a1.x; As[nxt][kq+1][r0+64] = a1.y; As[nxt][kq+2][r0+64] = a1.z; As[nxt][kq+3][r0+64] = a1.w;
            Bs[nxt][kq+0][r0]    = b0.x; Bs[nxt][kq+1][r0]    = b0.y; Bs[nxt][kq+2][r0]    = b0.z; Bs[nxt][kq+3][r0]    = b0.w;
            Bs[nxt][kq+0][r0+64] = b1.x; Bs[nxt][kq+1][r0+64] = b1.y; Bs[nxt][kq+2][r0+64] = b1.z; Bs[nxt][kq+3][r0+64] = b1.w;
            __syncthreads();
            cur = nxt;
        }
    }

    const int ac0 = bn + tn;            // first logical column of this fragment
#pragma unroll
    for (int i = 0; i < 8; ++i) {
        float accf[8];
#pragma unroll
        for (int j = 0; j < 4; ++j) {
            unsigned int lo, hi;
            asm("mov.b64 {%0, %1}, %2;" : "=r"(lo), "=r"(hi) : "l"(acc2[i][j]));
            accf[2*j]   = __uint_as_float(lo);
            accf[2*j+1] = __uint_as_float(hi);
        }
        const int row = bm + tm + i;
        if (ac0 < cellCols) {
            // interleaved LSTM-cell epilogue: 8 cols = 2 gate-quads = 2 hidden j's
            const float* addp = D ? (D + (size_t)row * (size_t)G4 + ac0)
                                  : (bias + ac0);
            const int jb = ac0 >> 2;
            float2 cv = *(const float2*)(cSt + (size_t)row * HH + jb);
            float* cvp = &cv.x;
            float hv[2];
#pragma unroll
            for (int q = 0; q < 2; ++q) {
                const float4 ad = *(const float4*)(addp + 4*q);
                const float xi = accf[4*q+0] + ad.x;
                const float xf = accf[4*q+1] + ad.y;
                const float xg = accf[4*q+2] + ad.z;
                const float xo = accf[4*q+3] + ad.w;
                const float cc = sigm(xf) * cvp[q] + sigm(xi) * tanhf(xg);
                cvp[q] = cc;
                hv[q] = sigm(xo) * tanhf(cc);
            }
            *(float2*)(cSt + (size_t)row * HH + jb) = cv;
            const float2 hvv = make_float2(hv[0], hv[1]);
            *(float2*)(hOut + (size_t)row * HH + jb) = hvv;
            if (encOut)
                *(float2*)(encOut + ((size_t)row * SS + sIdx) * HH + jb) = hvv;
        } else {
            float* Cp = C + (size_t)row * cstride + (ac0 - coloff);
#pragma unroll
            for (int q = 0; q < 2; ++q) {
                float4 v = make_float4(accf[4*q], accf[4*q+1],
                                       accf[4*q+2], accf[4*q+3]);
                if (bias) {
                    const float4 bb = *(const float4*)(bias + ac0 + 4*q);
                    v.x += bb.x; v.y += bb.y; v.z += bb.z; v.w += bb.w;
                }
                *(float4*)(Cp + 4*q) = v;
            }
        }
    }
}

// ---------------- prep kernels ----------------
// interleave permutation: new row r <- old row (r&3)*H + (r>>2)
__global__ void prep_misc(const float* __restrict__ ebih, const float* __restrict__ ebhh,
                          const float* __restrict__ dbih, const float* __restrict__ dbhh)
{
    const int t = blockIdx.x * blockDim.x + threadIdx.x;
    if (t < G4) {
        const int p = (t & 3) * HH + (t >> 2);
        g_bias_encI[t] = ebih[p] + ebhh[p];
        g_bias_catI[t] = dbih[p] + dbhh[p];
    } else if (t < GCAT) {
        g_bias_catI[t] = 0.f;
    }
    if (t < BB*SS) g_mask[t] = 0;
    if (t < BB*HH) g_c[t] = 0.f;
}

__global__ void prep_w(const float* __restrict__ eWih, const float* __restrict__ eWhh,
                       const float* __restrict__ dWhh, const float* __restrict__ W2)
{
    const int E4 = EE/4, H4 = HH/4;
    const int n1 = G4*E4, n2 = G4*H4, n3 = GCAT*H4;
    int t = blockIdx.x * blockDim.x + threadIdx.x;
    if (t < n1) {
        const int row = t / E4, c4 = t % E4;
        const int p = (row & 3) * HH + (row >> 2);
        ((float4*)g_WihP)[t] = ((const float4*)eWih)[(size_t)p * E4 + c4];
        return;
    }
    t -= n1;
    if (t < n2) {
        const int row = t / H4, c4 = t % H4;
        const int p = (row & 3) * HH + (row >> 2);
        ((float4*)g_WhhP)[t] = ((const float4*)eWhh)[(size_t)p * H4 + c4];
        return;
    }
    t -= n2;
    if (t < n3) {
        const int row = t / H4, c4 = t % H4;
        float4 v;
        if (row < G4) {
            const int p = (row & 3) * HH + (row >> 2);
            v = ((const float4*)dWhh)[(size_t)p * H4 + c4];
        } else {
            v = ((const float4*)W2)[(size_t)(row - G4) * H4 + c4];
        }
        ((float4*)g_WcatP)[t] = v;
    }
}

__global__ void gather_x(const int* __restrict__ input, const float* __restrict__ emb)
{
    const int E4 = EE / 4;
    const int t = blockIdx.x * blockDim.x + threadIdx.x;
    if (t >= SS * BB * E4) return;
    const int e4 = t % E4;
    const int r  = t / E4;      // r = s*BB + b
    const int b  = r % BB;
    const int s  = r / BB;
    const int tok = input[b * SS + s];
    ((float4*)g_X)[(size_t)r * E4 + e4] = ((const float4*)emb)[(size_t)tok * E4 + e4];
}

// standalone interleaved cell (for encoder step 0 and decoder step 0)
__global__ __launch_bounds__(256) void cell_i(const float* __restrict__ gates,
                                              int rowStride, float* hOut,
                                              float* encOut, int sIdx)
{
    const int t = blockIdx.x * blockDim.x + threadIdx.x;  // over B*H
    const int b = t >> 9;
    const int j = t & (HH - 1);
    const float4 gq = *(const float4*)(gates + (size_t)b * rowStride + 4*j);
    const float cn = sigm(gq.y) * g_c[t] + sigm(gq.x) * tanhf(gq.z);
    const float hn = sigm(gq.w) * tanhf(cn);
    g_c[t] = cn;
    hOut[t] = hn;
    if (encOut) encOut[((size_t)b * SS + sIdx) * HH + j] = hn;
}

// decoder init: c0 = final encoder h
__global__ void dec_init(const float* __restrict__ hSrc)
{
    const int t = blockIdx.x * blockDim.x + threadIdx.x;
    if (t < BB*HH) g_c[t] = hSrc[t];
}

// ---------------- fused scores + log_softmax + categorical + mask ----------------
__global__ __launch_bounds__(256) void score_sample(
    const float* __restrict__ blend2, int b2stride,
    const float* __restrict__ vt, float* probs, float* tour, int step)
{
    const int b = blockIdx.x;
    const int tid = threadIdx.x;
    const int wid = tid >> 5, lane = tid & 31;
    __shared__ float b2s[WW];
    __shared__ float vts[WW];
    __shared__ float sc[SS];
    __shared__ float smm[SS];
    __shared__ float smv[SS];
    __shared__ float red[2];

    b2s[tid] = blend2[(size_t)b * b2stride + tid];
    vts[tid] = vt[tid];
    __syncthreads();

    for (int s = wid; s < SS; s += 8) {
        const float* row = g_blend1 + ((size_t)b * SS + s) * WW;
        float a = 0.f;
#pragma unroll
        for (int w = lane; w < WW; w += 32)
            a += vts[w] * tanhf(row[w] + b2s[w]);
        a += __shfl_down_sync(0xffffffffu, a, 16);
        a += __shfl_down_sync(0xffffffffu, a,  8);
        a += __shfl_down_sync(0xffffffffu, a,  4);
        a += __shfl_down_sync(0xffffffffu, a,  2);
        a += __shfl_down_sync(0xffffffffu, a,  1);
        if (lane == 0) sc[s] = a;
    }
    __syncthreads();

    if (tid < SS) {
        const float sm_ = g_mask[b * SS + tid] ? -100000.0f : sc[tid];
        uint32_t K0, K1;
        derive_key(step, K0, K1);
        const uint32_t bits = rand_bits(K0, K1, (uint32_t)(b * SS + tid));
        float u = __uint_as_float((bits >> 9) | 0x3f800000u) - 1.0f;
        u = u + 1.17549435e-38f;
        if (u < 1.17549435e-38f) u = 1.17549435e-38f;
        const float g = -logf(-logf(u));
        smm[tid] = sm_;
        smv[tid] = sm_ + g;
    }
    __syncthreads();

    if (tid == 0) {
        float best = smv[0]; int bi = 0; float mx = smm[0];
        for (int s = 1; s < SS; ++s) {
            if (smv[s] > best) { best = smv[s]; bi = s; }
            if (smm[s] > mx) mx = smm[s];
        }
        float sum = 0.f;
        for (int s = 0; s < SS; ++s) sum += expf(smm[s] - mx);
        red[0] = mx; red[1] = logf(sum);
        g_mask[b * SS + bi] = 1;
        if (tour) tour[(size_t)b * LL + step] = (float)bi;
    }
    __syncthreads();

    if (tid < SS && probs) {
        probs[((size_t)b * LL + step) * SS + tid] = (smm[tid] - red[0]) - red[1];
    }
}

// ---------------- launch ----------------
extern "C" void kernel_launch(void* const* d_in, const int* in_sizes, int n_in,
                              void* d_out, int out_size)
{
    if (n_in < 13) return;
    const int*   input = (const int*)  d_in[0];
    const float* emb   = (const float*)d_in[1];
    const float* eWih  = (const float*)d_in[2];
    const float* eWhh  = (const float*)d_in[3];
    const float* ebih  = (const float*)d_in[4];
    const float* ebhh  = (const float*)d_in[5];
    /* d_in[6] = dec_Wih : unused (decoder input is all zeros) */
    const float* dWhh  = (const float*)d_in[7];
    const float* dbih  = (const float*)d_in[8];
    const float* dbhh  = (const float*)d_in[9];
    const float* W1    = (const float*)d_in[10];
    const float* W2    = (const float*)d_in[11];
    const float* vt    = (const float*)d_in[12];

    float *pX, *pGates, *pEnc, *pB1, *pB2, *pC,
          *pBEI, *pBCI, *pWihP, *pWhhP, *pWcatP, *pH0, *pH1;
    cudaGetSymbolAddress((void**)&pX,     g_X);
    cudaGetSymbolAddress((void**)&pGates, g_gates);
    cudaGetSymbolAddress((void**)&pEnc,   g_enc);
    cudaGetSymbolAddress((void**)&pB1,    g_blend1);
    cudaGetSymbolAddress((void**)&pB2,    g_blend2);
    cudaGetSymbolAddress((void**)&pC,     g_c);
    cudaGetSymbolAddress((void**)&pBEI,   g_bias_encI);
    cudaGetSymbolAddress((void**)&pBCI,   g_bias_catI);
    cudaGetSymbolAddress((void**)&pWihP,  g_WihP);
    cudaGetSymbolAddress((void**)&pWhhP,  g_WhhP);
    cudaGetSymbolAddress((void**)&pWcatP, g_WcatP);
    cudaGetSymbolAddress((void**)&pH0,    g_h0);
    cudaGetSymbolAddress((void**)&pH1,    g_h1);
    float* hb[2] = {pH0, pH1};

    const size_t np = (size_t)BB * LL * SS;
    const size_t nt = (size_t)BB * LL;
    float* probs = ((size_t)out_size >= np)      ? (float*)d_out        : nullptr;
    float* tour  = ((size_t)out_size >= np + nt) ? ((float*)d_out + np) : nullptr;

    // prep
    prep_misc<<<4096, 256>>>(ebih, ebhh, dbih, dbhh);
    prep_w<<<2688, 256>>>(eWih, eWhh, dWhh, W2);
    gather_x<<<25600, 256>>>(input, emb);

    // encoder input projections (interleaved gates + bias), all timesteps
    gemm_fused<<<dim3(16, 800), 256>>>(pX, pWihP, pGates, G4, 0,
                                       nullptr, pBEI,
                                       nullptr, nullptr, nullptr, 0,
                                       0, EE);

    // encoder step 0: gates == input projection (h=0)
    cell_i<<<4096, 256>>>(pGates, G4, hb[0], pEnc, 0);

    // encoder recurrence with fused cell epilogue (256 CTAs = 1 wave @ occ2)
    for (int s = 1; s < SS; ++s) {
        gemm_fused<<<dim3(16, 16), 256>>>(hb[(s-1)&1], pWhhP, nullptr, 0, 0,
                                          pGates + (size_t)s * BB * G4, nullptr,
                                          pC, hb[s&1], pEnc, s,
                                          G4, HH);
    }

    // decoder init: c0 = enc h_final (in hb[1] after s=49), h implicit 0
    dec_init<<<4096, 256>>>(hb[1]);
    cell_i<<<4096, 256>>>(pBCI, 0, hb[0], nullptr, 0);   // -> hd_1

    // blend1 = enc_states @ W1^T (loop-invariant)
    gemm_fused<<<dim3(2, 800), 256>>>(pEnc, W1, pB1, WW, 0,
                                      nullptr, nullptr,
                                      nullptr, nullptr, nullptr, 0,
                                      0, HH);

    // decoder: one wide fused GEMM per step (288 CTAs = 1 wave @ occ2):
    //   cols [0,2048): interleaved gates -> cell -> h_{k+2}
    //   cols [2048,2304): blend2_k = h_{k+1} @ W2^T
    for (int k = 0; k < LL; ++k) {
        gemm_fused<<<dim3(18, 16), 256>>>(hb[k&1], pWcatP, pB2, WW, G4,
                                          nullptr, pBCI,
                                          pC, hb[(k+1)&1], nullptr, 0,
                                          G4, HH);
        score_sample<<<BB, 256>>>(pB2, WW, vt, probs, tour, k);
    }
}

// round 16
// speedup vs baseline: 1.6162x; 1.0645x over previous
#include <cuda_runtime.h>
#include <cstdint>
#include <math.h>

typedef unsigned long long ull;

// Problem dims (fixed by the reference)
#define BB 2048
#define SS 50
#define EE 256
#define HH 512
#define G4 (4*HH)       // 2048
#define WW 256
#define LL 50
#define GCAT (G4 + WW)  // 2304 : [interleaved dec gates | blend2]

#define PARTITIONABLE 1

// ---------------- scratch (static device globals; no allocation) ----------------
__device__ __align__(16) float g_X[SS*BB*EE];        // gathered embeddings, [s][b][e]
__device__ __align__(16) float g_gates[SS*BB*G4];    // encoder input gate pre-acts (interleaved)
__device__ __align__(16) float g_enc[BB*SS*HH];      // encoder hidden states [b][s][h]
__device__ __align__(16) float g_blend1[BB*SS*WW];   // W1 @ enc_states, [b][s][w]
__device__ __align__(16) float g_blend2[2][BB*WW];   // double-buffered for stream overlap
__device__ __align__(16) float g_h0[BB*HH];
__device__ __align__(16) float g_h1[BB*HH];
__device__ __align__(16) float g_c[BB*HH];
__device__ __align__(16) float g_bias_encI[G4];      // interleaved enc bias
__device__ __align__(16) float g_bias_catI[GCAT];    // [interleaved dec bias | 0]
__device__ __align__(16) float g_WihP[G4*EE];        // interleaved-row enc_Wih
__device__ __align__(16) float g_WhhP[G4*HH];        // interleaved-row enc_Whh
__device__ __align__(16) float g_WcatP[GCAT*HH];     // [interleaved dec_Whh ; W2]
__device__ unsigned char g_mask[BB*SS];

// ---------------- static stream/event resources (created once, pre-capture) ----
struct OverlapRes {
    cudaStream_t s1 = nullptr;
    cudaEvent_t evG[LL], evS[LL];
    bool ok = false;
    OverlapRes() {
        if (cudaStreamCreateWithFlags(&s1, cudaStreamNonBlocking) != cudaSuccess) return;
        for (int i = 0; i < LL; ++i) {
            if (cudaEventCreateWithFlags(&evG[i], cudaEventDisableTiming) != cudaSuccess) return;
            if (cudaEventCreateWithFlags(&evS[i], cudaEventDisableTiming) != cudaSuccess) return;
        }
        ok = true;
    }
};
static OverlapRes g_res;

// ---------------- Threefry-2x32-20 (exact JAX algorithm) ----------------
__device__ __forceinline__ uint32_t rotl32(uint32_t v, int r) {
    return (v << r) | (v >> (32 - r));
}

__device__ __forceinline__ void tf2x32(uint32_t k0, uint32_t k1,
                                       uint32_t& x0, uint32_t& x1) {
    const uint32_t ks2 = k0 ^ k1 ^ 0x1BD11BDAu;
    x0 += k0; x1 += k1;
    x0 += x1; x1 = rotl32(x1, 13); x1 ^= x0;
    x0 += x1; x1 = rotl32(x1, 15); x1 ^= x0;
    x0 += x1; x1 = rotl32(x1, 26); x1 ^= x0;
    x0 += x1; x1 = rotl32(x1,  6); x1 ^= x0;
    x0 += k1; x1 += ks2 + 1u;
    x0 += x1; x1 = rotl32(x1, 17); x1 ^= x0;
    x0 += x1; x1 = rotl32(x1, 29); x1 ^= x0;
    x0 += x1; x1 = rotl32(x1, 16); x1 ^= x0;
    x0 += x1; x1 = rotl32(x1, 24); x1 ^= x0;
    x0 += ks2; x1 += k0 + 2u;
    x0 += x1; x1 = rotl32(x1, 13); x1 ^= x0;
    x0 += x1; x1 = rotl32(x1, 15); x1 ^= x0;
    x0 += x1; x1 = rotl32(x1, 26); x1 ^= x0;
    x0 += x1; x1 = rotl32(x1,  6); x1 ^= x0;
    x0 += k0; x1 += k1 + 3u;
    x0 += x1; x1 = rotl32(x1, 17); x1 ^= x0;
    x0 += x1; x1 = rotl32(x1, 29); x1 ^= x0;
    x0 += x1; x1 = rotl32(x1, 16); x1 ^= x0;
    x0 += x1; x1 = rotl32(x1, 24); x1 ^= x0;
    x0 += k1; x1 += ks2 + 4u;
    x0 += x1; x1 = rotl32(x1, 13); x1 ^= x0;
    x0 += x1; x1 = rotl32(x1, 15); x1 ^= x0;
    x0 += x1; x1 = rotl32(x1, 26); x1 ^= x0;
    x0 += x1; x1 = rotl32(x1,  6); x1 ^= x0;
    x0 += ks2; x1 += k0 + 5u;
}

__device__ __forceinline__ void derive_key(int step, uint32_t& K0, uint32_t& K1) {
#if PARTITIONABLE
    uint32_t a = 0u, b = (uint32_t)step;
    tf2x32(0u, 42u, a, b);
    K0 = a; K1 = b;
#else
    const int la = (step < 25) ? 2*step : 2*step - 50;
    uint32_t a0 = (uint32_t)la,     a1 = (uint32_t)(la + 50);
    uint32_t b0 = (uint32_t)(la+1), b1 = (uint32_t)(la + 51);
    tf2x32(0u, 42u, a0, a1);
    tf2x32(0u, 42u, b0, b1);
    if (step < 25) { K0 = a0; K1 = b0; } else { K0 = a1; K1 = b1; }
#endif
}

__device__ __forceinline__ uint32_t rand_bits(uint32_t K0, uint32_t K1, uint32_t i) {
#if PARTITIONABLE
    uint32_t x0 = 0u, x1 = i;
    tf2x32(K0, K1, x0, x1);
    return x0 ^ x1;
#else
    const uint32_t half = (BB*SS) / 2;
    if (i < half) { uint32_t x0 = i, x1 = i + half; tf2x32(K0, K1, x0, x1); return x0; }
    else          { uint32_t x0 = i - half, x1 = i; tf2x32(K0, K1, x0, x1); return x1; }
#endif
}

__device__ __forceinline__ float sigm(float x) { return 1.f / (1.f + expf(-x)); }

// split-quad column mapping for conflict-free B fragment reads:
// logical col c -> smem float index ((c&4)<<4) + ((c>>3)<<2) + (c&3)
__device__ __forceinline__ int bcol(int c) {
    return ((c & 4) << 4) + ((c >> 3) << 2) + (c & 3);
}

// ---------------- fused GEMM (+ optional LSTM-cell epilogue) ----------------
// C-logical[M,N] = A[M,K] @ Bw[N,K]^T. Tile 128x128, Kc=16, 256 threads,
// 8x8 micro-tile with packed fma.rn.f32x2, double-buffered smem, 2 CTAs/SM.
// B stored in split-quad layout (bcol) so fragment LDS.128s are conflict-free.
// Columns < cellCols: interleaved LSTM gates (col=4j+gate):
//   quad += (D ? D[row*G4+col] : bias[col]); cell -> write c, hOut, encOut.
// Columns >= cellCols: plain write C[row*cstride + col - coloff] (+bias[col]).
__global__ __launch_bounds__(256, 2) void gemm_fused(
    const float* __restrict__ A, const float* __restrict__ Bw,
    float* C, int cstride, int coloff,
    const float* __restrict__ D, const float* __restrict__ bias,
    float* cSt, float* hOut, float* encOut, int sIdx,
    int cellCols, int K)
{
    __shared__ float As[2][16][128];
    __shared__ float Bs[2][16][128];
    const int tid = threadIdx.x;
    const int bm = blockIdx.y << 7;
    const int bn = blockIdx.x << 7;

    const int r0 = tid >> 2;            // 0..63
    const int kq = (tid & 3) << 2;      // 0,4,8,12
    const int bc0 = bcol(r0);           // split-quad store index for col r0
    const int bc1 = bc0 + 32;           // for col r0+64

    const float* Ap0 = A  + (size_t)(bm + r0)      * K + kq;
    const float* Ap1 = A  + (size_t)(bm + r0 + 64) * K + kq;
    const float* Bp0 = Bw + (size_t)(bn + r0)      * K + kq;
    const float* Bp1 = Bw + (size_t)(bn + r0 + 64) * K + kq;

    const int tm = (tid >> 4) << 3;     // row micro-offset
    const int tn = (tid & 15) << 3;     // col micro-offset (logical)
    const int t4 = (tid & 15) << 2;     // split-quad fragment base

    ull acc2[8][4];
#pragma unroll
    for (int i = 0; i < 8; ++i)
#pragma unroll
        for (int j = 0; j < 4; ++j) acc2[i][j] = 0ull;

    const int nk = K >> 4;

    float4 a0 = *(const float4*)Ap0;
    float4 a1 = *(const float4*)Ap1;
    float4 b0 = *(const float4*)Bp0;
    float4 b1 = *(const float4*)Bp1;

    int cur = 0;
    As[0][kq+0][r0]    = a0.x; As[0][kq+1][r0]    = a0.y; As[0][kq+2][r0]    = a0.z; As[0][kq+3][r0]    = a0.w;
    As[0][kq+0][r0+64] = a1.x; As[0][kq+1][r0+64] = a1.y; As[0][kq+2][r0+64] = a1.z; As[0][kq+3][r0+64] = a1.w;
    Bs[0][kq+0][bc0]   = b0.x; Bs[0][kq+1][bc0]   = b0.y; Bs[0][kq+2][bc0]   = b0.z; Bs[0][kq+3][bc0]   = b0.w;
    Bs[0][kq+0][bc1]   = b1.x; Bs[0][kq+1][bc1]   = b1.y; Bs[0][kq+2][bc1]   = b1.z; Bs[0][kq+3][bc1]   = b1.w;
    __syncthreads();

    for (int kt = 0; kt < nk; ++kt) {
        const bool hasNext = (kt + 1 < nk);
        if (hasNext) {
            const int off = (kt + 1) << 4;
            a0 = *(const float4*)(Ap0 + off);
            a1 = *(const float4*)(Ap1 + off);
            b0 = *(const float4*)(Bp0 + off);
            b1 = *(const float4*)(Bp1 + off);
        }
#pragma unroll
        for (int kk = 0; kk < 16; ++kk) {
            const float4 x0 = *(const float4*)&As[cur][kk][tm];
            const float4 x1 = *(const float4*)&As[cur][kk][tm + 4];
            const ulonglong2 q0 = *(const ulonglong2*)&Bs[cur][kk][t4];
            const ulonglong2 q1 = *(const ulonglong2*)&Bs[cur][kk][64 + t4];
            ull bpk[4];
            bpk[0] = q0.x; bpk[1] = q0.y; bpk[2] = q1.x; bpk[3] = q1.y;
            const float av[8] = {x0.x,x0.y,x0.z,x0.w,x1.x,x1.y,x1.z,x1.w};
#pragma unroll
            for (int i = 0; i < 8; ++i) {
                ull a2;
                const unsigned int ai = __float_as_uint(av[i]);
                asm("mov.b64 %0, {%1, %2};" : "=l"(a2) : "r"(ai), "r"(ai));
#pragma unroll
                for (int j = 0; j < 4; ++j) {
                    asm("fma.rn.f32x2 %0, %1, %2, %0;"
                        : "+l"(acc2[i][j]) : "l"(a2), "l"(bpk[j]));
                }
            }
        }
        if (hasNext) {
            const int nxt = cur ^ 1;
            As[nxt][kq+0][r0]    = a0.x; As[nxt][kq+1][r0]    = a0.y; As[nxt][kq+2][r0]    = a0.z; As[nxt][kq+3][r0]    = a0.w;
            As[nxt][kq+0][r0+64] = a1.x; As[nxt][kq+1][r0+64] = a1.y; As[nxt][kq+2][r0+64] = a1.z; As[nxt][kq+3][r0+64] = a1.w;
            Bs[nxt][kq+0][bc0]   = b0.x; Bs[nxt][kq+1][bc0]   = b0.y; Bs[nxt][kq+2][bc0]   = b0.z; Bs[nxt][kq+3][bc0]   = b0.w;
            Bs[nxt][kq+0][bc1]   = b1.x; Bs[nxt][kq+1][bc1]   = b1.y; Bs[nxt][kq+2][bc1]   = b1.z; Bs[nxt][kq+3][bc1]   = b1.w;
            __syncthreads();
            cur = nxt;
        }
    }

    const int ac0 = bn + tn;            // first logical column of this fragment
#pragma unroll
    for (int i = 0; i < 8; ++i) {
        float accf[8];
#pragma unroll
        for (int j = 0; j < 4; ++j) {
            unsigned int lo, hi;
            asm("mov.b64 {%0, %1}, %2;" : "=r"(lo), "=r"(hi) : "l"(acc2[i][j]));
            accf[2*j]   = __uint_as_float(lo);
            accf[2*j+1] = __uint_as_float(hi);
        }
        const int row = bm + tm + i;
        if (ac0 < cellCols) {
            // interleaved LSTM-cell epilogue: 8 cols = 2 gate-quads = 2 hidden j's
            const float* addp = D ? (D + (size_t)row * (size_t)G4 + ac0)
                                  : (bias + ac0);
            const int jb = ac0 >> 2;
            float2 cv = *(const float2*)(cSt + (size_t)row * HH + jb);
            float* cvp = &cv.x;
            float hv[2];
#pragma unroll
            for (int q = 0; q < 2; ++q) {
                const float4 ad = *(const float4*)(addp + 4*q);
                const float xi = accf[4*q+0] + ad.x;
                const float xf = accf[4*q+1] + ad.y;
                const float xg = accf[4*q+2] + ad.z;
                const float xo = accf[4*q+3] + ad.w;
                const float cc = sigm(xf) * cvp[q] + sigm(xi) * tanhf(xg);
                cvp[q] = cc;
                hv[q] = sigm(xo) * tanhf(cc);
            }
            *(float2*)(cSt + (size_t)row * HH + jb) = cv;
            const float2 hvv = make_float2(hv[0], hv[1]);
            *(float2*)(hOut + (size_t)row * HH + jb) = hvv;
            if (encOut)
                *(float2*)(encOut + ((size_t)row * SS + sIdx) * HH + jb) = hvv;
        } else {
            float* Cp = C + (size_t)row * cstride + (ac0 - coloff);
#pragma unroll
            for (int q = 0; q < 2; ++q) {
                float4 v = make_float4(accf[4*q], accf[4*q+1],
                                       accf[4*q+2], accf[4*q+3]);
                if (bias) {
                    const float4 bb = *(const float4*)(bias + ac0 + 4*q);
                    v.x += bb.x; v.y += bb.y; v.z += bb.z; v.w += bb.w;
                }
                *(float4*)(Cp + 4*q) = v;
            }
        }
    }
}

// ---------------- prep kernels ----------------
// interleave permutation: new row r <- old row (r&3)*H + (r>>2)
__global__ void prep_misc(const float* __restrict__ ebih, const float* __restrict__ ebhh,
                          const float* __restrict__ dbih, const float* __restrict__ dbhh)
{
    const int t = blockIdx.x * blockDim.x + threadIdx.x;
    if (t < G4) {
        const int p = (t & 3) * HH + (t >> 2);
        g_bias_encI[t] = ebih[p] + ebhh[p];
        g_bias_catI[t] = dbih[p] + dbhh[p];
    } else if (t < GCAT) {
        g_bias_catI[t] = 0.f;
    }
    if (t < BB*SS) g_mask[t] = 0;
    if (t < BB*HH) g_c[t] = 0.f;
}

__global__ void prep_w(const float* __restrict__ eWih, const float* __restrict__ eWhh,
                       const float* __restrict__ dWhh, const float* __restrict__ W2)
{
    const int E4 = EE/4, H4 = HH/4;
    const int n1 = G4*E4, n2 = G4*H4, n3 = GCAT*H4;
    int t = blockIdx.x * blockDim.x + threadIdx.x;
    if (t < n1) {
        const int row = t / E4, c4 = t % E4;
        const int p = (row & 3) * HH + (row >> 2);
        ((float4*)g_WihP)[t] = ((const float4*)eWih)[(size_t)p * E4 + c4];
        return;
    }
    t -= n1;
    if (t < n2) {
        const int row = t / H4, c4 = t % H4;
        const int p = (row & 3) * HH + (row >> 2);
        ((float4*)g_WhhP)[t] = ((const float4*)eWhh)[(size_t)p * H4 + c4];
        return;
    }
    t -= n2;
    if (t < n3) {
        const int row = t / H4, c4 = t % H4;
        float4 v;
        if (row < G4) {
            const int p = (row & 3) * HH + (row >> 2);
            v = ((const float4*)dWhh)[(size_t)p * H4 + c4];
        } else {
            v = ((const float4*)W2)[(size_t)(row - G4) * H4 + c4];
        }
        ((float4*)g_WcatP)[t] = v;
    }
}

__global__ void gather_x(const int* __restrict__ input, const float* __restrict__ emb)
{
    const int E4 = EE / 4;
    const int t = blockIdx.x * blockDim.x + threadIdx.x;
    if (t >= SS * BB * E4) return;
    const int e4 = t % E4;
    const int r  = t / E4;      // r = s*BB + b
    const int b  = r % BB;
    const int s  = r / BB;
    const int tok = input[b * SS + s];
    ((float4*)g_X)[(size_t)r * E4 + e4] = ((const float4*)emb)[(size_t)tok * E4 + e4];
}

// standalone interleaved cell (for encoder step 0 and decoder step 0)
__global__ __launch_bounds__(256) void cell_i(const float* __restrict__ gates,
                                              int rowStride, float* hOut,
                                              float* encOut, int sIdx)
{
    const int t = blockIdx.x * blockDim.x + threadIdx.x;  // over B*H
    const int b = t >> 9;
    const int j = t & (HH - 1);
    const float4 gq = *(const float4*)(gates + (size_t)b * rowStride + 4*j);
    const float cn = sigm(gq.y) * g_c[t] + sigm(gq.x) * tanhf(gq.z);
    const float hn = sigm(gq.w) * tanhf(cn);
    g_c[t] = cn;
    hOut[t] = hn;
    if (encOut) encOut[((size_t)b * SS + sIdx) * HH + j] = hn;
}

// decoder init: c0 = final encoder h
__global__ void dec_init(const float* __restrict__ hSrc)
{
    const int t = blockIdx.x * blockDim.x + threadIdx.x;
    if (t < BB*HH) g_c[t] = hSrc[t];
}

// ---------------- fused scores + log_softmax + categorical + mask ----------------
__global__ __launch_bounds__(256) void score_sample(
    const float* __restrict__ blend2, int b2stride,
    const float* __restrict__ vt, float* probs, float* tour, int step)
{
    const int b = blockIdx.x;
    const int tid = threadIdx.x;
    const int wid = tid >> 5, lane = tid & 31;
    __shared__ float b2s[WW];
    __shared__ float vts[WW];
    __shared__ float sc[SS];
    __shared__ float smm[SS];
    __shared__ float smv[SS];
    __shared__ float red[2];

    b2s[tid] = blend2[(size_t)b * b2stride + tid];
    vts[tid] = vt[tid];
    __syncthreads();

    for (int s = wid; s < SS; s += 8) {
        const float* row = g_blend1 + ((size_t)b * SS + s) * WW;
        float a = 0.f;
#pragma unroll
        for (int w = lane; w < WW; w += 32)
            a += vts[w] * tanhf(row[w] + b2s[w]);
        a += __shfl_down_sync(0xffffffffu, a, 16);
        a += __shfl_down_sync(0xffffffffu, a,  8);
        a += __shfl_down_sync(0xffffffffu, a,  4);
        a += __shfl_down_sync(0xffffffffu, a,  2);
        a += __shfl_down_sync(0xffffffffu, a,  1);
        if (lane == 0) sc[s] = a;
    }
    __syncthreads();

    if (tid < SS) {
        const float sm_ = g_mask[b * SS + tid] ? -100000.0f : sc[tid];
        uint32_t K0, K1;
        derive_key(step, K0, K1);
        const uint32_t bits = rand_bits(K0, K1, (uint32_t)(b * SS + tid));
        float u = __uint_as_float((bits >> 9) | 0x3f800000u) - 1.0f;
        u = u + 1.17549435e-38f;
        if (u < 1.17549435e-38f) u = 1.17549435e-38f;
        const float g = -logf(-logf(u));
        smm[tid] = sm_;
        smv[tid] = sm_ + g;
    }
    __syncthreads();

    if (tid == 0) {
        float best = smv[0]; int bi = 0; float mx = smm[0];
        for (int s = 1; s < SS; ++s) {
            if (smv[s] > best) { best = smv[s]; bi = s; }
            if (smm[s] > mx) mx = smm[s];
        }
        float sum = 0.f;
        for (int s = 0; s < SS; ++s) sum += expf(smm[s] - mx);
        red[0] = mx; red[1] = logf(sum);
        g_mask[b * SS + bi] = 1;
        if (tour) tour[(size_t)b * LL + step] = (float)bi;
    }
    __syncthreads();

    if (tid < SS && probs) {
        probs[((size_t)b * LL + step) * SS + tid] = (smm[tid] - red[0]) - red[1];
    }
}

// ---------------- launch ----------------
extern "C" void kernel_launch(void* const* d_in, const int* in_sizes, int n_in,
                              void* d_out, int out_size)
{
    if (n_in < 13) return;
    const int*   input = (const int*)  d_in[0];
    const float* emb   = (const float*)d_in[1];
    const float* eWih  = (const float*)d_in[2];
    const float* eWhh  = (const float*)d_in[3];
    const float* ebih  = (const float*)d_in[4];
    const float* ebhh  = (const float*)d_in[5];
    /* d_in[6] = dec_Wih : unused (decoder input is all zeros) */
    const float* dWhh  = (const float*)d_in[7];
    const float* dbih  = (const float*)d_in[8];
    const float* dbhh  = (const float*)d_in[9];
    const float* W1    = (const float*)d_in[10];
    const float* W2    = (const float*)d_in[11];
    const float* vt    = (const float*)d_in[12];

    float *pX, *pGates, *pEnc, *pB1, *pB2, *pC,
          *pBEI, *pBCI, *pWihP, *pWhhP, *pWcatP, *pH0, *pH1;
    cudaGetSymbolAddress((void**)&pX,     g_X);
    cudaGetSymbolAddress((void**)&pGates, g_gates);
    cudaGetSymbolAddress((void**)&pEnc,   g_enc);
    cudaGetSymbolAddress((void**)&pB1,    g_blend1);
    cudaGetSymbolAddress((void**)&pB2,    g_blend2);
    cudaGetSymbolAddress((void**)&pC,     g_c);
    cudaGetSymbolAddress((void**)&pBEI,   g_bias_encI);
    cudaGetSymbolAddress((void**)&pBCI,   g_bias_catI);
    cudaGetSymbolAddress((void**)&pWihP,  g_WihP);
    cudaGetSymbolAddress((void**)&pWhhP,  g_WhhP);
    cudaGetSymbolAddress((void**)&pWcatP, g_WcatP);
    cudaGetSymbolAddress((void**)&pH0,    g_h0);
    cudaGetSymbolAddress((void**)&pH1,    g_h1);
    float* hb[2] = {pH0, pH1};

    const size_t np = (size_t)BB * LL * SS;
    const size_t nt = (size_t)BB * LL;
    float* probs = ((size_t)out_size >= np)      ? (float*)d_out        : nullptr;
    float* tour  = ((size_t)out_size >= np + nt) ? ((float*)d_out + np) : nullptr;

    // prep
    prep_misc<<<4096, 256>>>(ebih, ebhh, dbih, dbhh);
    prep_w<<<2688, 256>>>(eWih, eWhh, dWhh, W2);
    gather_x<<<25600, 256>>>(input, emb);

    // encoder input projections (interleaved gates + bias), all timesteps
    gemm_fused<<<dim3(16, 800), 256>>>(pX, pWihP, pGates, G4, 0,
                                       nullptr, pBEI,
                                       nullptr, nullptr, nullptr, 0,
                                       0, EE);

    // encoder step 0: gates == input projection (h=0)
    cell_i<<<4096, 256>>>(pGates, G4, hb[0], pEnc, 0);

    // encoder recurrence with fused cell epilogue (256 CTAs = 1 wave @ occ2)
    for (int s = 1; s < SS; ++s) {
        gemm_fused<<<dim3(16, 16), 256>>>(hb[(s-1)&1], pWhhP, nullptr, 0, 0,
                                          pGates + (size_t)s * BB * G4, nullptr,
                                          pC, hb[s&1], pEnc, s,
                                          G4, HH);
    }

    // decoder init: c0 = enc h_final (in hb[1] after s=49), h implicit 0
    dec_init<<<4096, 256>>>(hb[1]);
    cell_i<<<4096, 256>>>(pBCI, 0, hb[0], nullptr, 0);   // -> hd_1

    // blend1 = enc_states @ W1^T (loop-invariant)
    gemm_fused<<<dim3(2, 800), 256>>>(pEnc, W1, pB1, WW, 0,
                                      nullptr, nullptr,
                                      nullptr, nullptr, nullptr, 0,
                                      0, HH);

    // decoder: GEMM chain on stream 0, score chain on side stream s1.
    // score_k depends on GEMM_k (blend2 buf k&1) + score_{k-1} (mask);
    // GEMM_{k+2} waits score_k only for blend2 buffer reuse (WAR).
    const bool ov = g_res.ok;
    for (int k = 0; k < LL; ++k) {
        float* b2k = pB2 + (size_t)(k & 1) * BB * WW;
        if (ov && k >= 2) cudaStreamWaitEvent(0, g_res.evS[k-2], 0);
        gemm_fused<<<dim3(18, 16), 256>>>(hb[k&1], pWcatP, b2k, WW, G4,
                                          nullptr, pBCI,
                                          pC, hb[(k+1)&1], nullptr, 0,
                                          G4, HH);
        if (ov) {
            cudaEventRecord(g_res.evG[k], 0);
            cudaStreamWaitEvent(g_res.s1, g_res.evG[k], 0);
            score_sample<<<BB, 256, 0, g_res.s1>>>(b2k, WW, vt, probs, tour, k);
            cudaEventRecord(g_res.evS[k], g_res.s1);
        } else {
            score_sample<<<BB, 256>>>(b2k, WW, vt, probs, tour, k);
        }
    }
    if (ov) cudaStreamWaitEvent(0, g_res.evS[LL-1], 0);
}